// round 5
// baseline (speedup 1.0000x reference)
#include <cuda_runtime.h>
#include <cuda_bf16.h>

#define BB 2
#define H 256
#define W 832
#define NPIX (H*W)

#define TS 32
#define HALO 10
#define TY_N (H/TS)          // 8
#define TX_N (W/TS)          // 26
#define NTILE (TY_N*TX_N)    // 208 per batch
#define TCAP 352             // >= 18*18 = 324 (kept points pairwise Chebyshev >= 3 in 52x52 halo)

// per-tile binned active-point lists (zero-initialized at module load; k_diffuse re-zeroes counts)
__device__ int    g_tcnt[BB*NTILE];
__device__ int    g_tpos[BB*NTILE*TCAP];     // (i<<16)|j
__device__ float2 g_tdxy[BB*NTILE*TCAP];

// on-demand orientation: circular 3x3 box blur + edge-clamped np.gradient -> (cos, sin) of atan2
__device__ __forceinline__ void orient(const float* __restrict__ m, int i, int j,
                                       float& cs, float& ss) {
    float patch[5][5];
#pragma unroll
    for (int r = 0; r < 5; r++) {
        int ii = i + r - 2; ii += (ii < 0) ? H : 0; ii -= (ii >= H) ? H : 0;
#pragma unroll
        for (int c = 0; c < 5; c++) {
            int jj = j + c - 2; jj += (jj < 0) ? W : 0; jj -= (jj >= W) ? W : 0;
            patch[r][c] = m[ii*W + jj];
        }
    }
#define BLUR_AT(di, dj) (patch[1+di][1+dj] + patch[1+di][2+dj] + patch[1+di][3+dj] \
                       + patch[2+di][1+dj] + patch[2+di][2+dj] + patch[2+di][3+dj] \
                       + patch[3+di][1+dj] + patch[3+di][2+dj] + patch[3+di][3+dj])
    float byp = BLUR_AT(1, 0), bym = BLUR_AT(-1, 0), bc = BLUR_AT(0, 0);
    float bxp = BLUR_AT(0, 1), bxm = BLUR_AT(0, -1);
#undef BLUR_AT
    float gyv = (i == 0) ? (byp - bc) : (i == H-1) ? (bc - bym) : 0.5f * (byp - bym);
    float gxv = (j == 0) ? (bxp - bc) : (j == W-1) ? (bc - bxm) : 0.5f * (bxp - bxm);
    float r = sqrtf(gxv*gxv + gyv*gyv);
    if (r > 0.f) { cs = gxv / r; ss = gyv / r; }
    else         { cs = 1.f;     ss = 0.f;     }   // atan2(0,0)=0
}

// ---------------- K1: fused sparsify + correspondence search + tile binning ----------------
__global__ void __launch_bounds__(256) k_seed(const float* __restrict__ src,
                                              const float* __restrict__ dst,
                                              const int* __restrict__ xx,
                                              const int* __restrict__ yy, int K) {
    __shared__ int s_pos[640];
    __shared__ int s_cnt;
    __shared__ int s_xx[112], s_yy[112];

    int b = blockIdx.y;
    int tid = threadIdx.x;
    const float* S = src + b*NPIX;
    const float* D = dst + b*NPIX;

    if (tid == 0) s_cnt = 0;
    if (tid < K) { s_xx[tid] = xx[tid]; s_yy[tid] = yy[tid]; }
    __syncthreads();

    // phase 1: vectorized edge scan + keep-test (min linear index edge in 5x5 window)
    int p0 = (blockIdx.x * 256 + tid) * 4;
    float4 v4 = *reinterpret_cast<const float4*>(S + p0);
    float vv[4] = {v4.x, v4.y, v4.z, v4.w};
#pragma unroll
    for (int c4 = 0; c4 < 4; c4++) {
        if (vv[c4] > 0.5f) {
            int p = p0 + c4;
            int i = p / W, j = p - i*W;
            bool kept = true;
#pragma unroll
            for (int a = -2; a <= 2; a++) {
                int ii = i + a;
                if (ii < 0 || ii >= H) continue;
#pragma unroll
                for (int c = -2; c <= 2; c++) {
                    int jj = j + c;
                    if (jj < 0 || jj >= W) continue;
                    int q = ii*W + jj;
                    if (q < p && S[q] > 0.5f) kept = false;
                }
            }
            if (kept) { int idx = atomicAdd(&s_cnt, 1); s_pos[idx] = p; }
        }
    }
    __syncthreads();
    int n = s_cnt;

    // phase 2: warp per kept point, K offsets over lanes
    int warp = tid >> 5, lane = tid & 31;
    for (int pt = warp; pt < n; pt += 8) {
        int pp = s_pos[pt];
        int pi = pp / W, pj = pp - (pp / W) * W;
        float cs, ssv;
        orient(S, pi, pj, cs, ssv);   // uniform addresses across warp -> broadcast loads
        float best = 1e9f; int bk = 0x7fffffff;
        for (int k = lane; k < K; k += 32) {
            int ox = s_xx[k], oy = s_yy[k];
            int ii = pi + oy, jj = pj + ox;
            if (ii >= 0 && ii < H && jj >= 0 && jj < W) {
                int q = ii*W + jj;
                if (D[q] > 0.5f) {
                    float cd, sd;
                    orient(D, ii, jj, cd, sd);   // rare (~2 hits/point)
                    float ang = 1.0f - (cs*cd + ssv*sd);
                    float sc = 20.0f * sqrtf((float)(ox*ox + oy*oy)) + 10.5f * ang;
                    if (sc < best) { best = sc; bk = k; }
                }
            }
        }
        // warp lexicographic (score, k) min -> global first-index-of-min (argmin semantics)
#pragma unroll
        for (int o = 16; o; o >>= 1) {
            float s2 = __shfl_xor_sync(0xffffffffu, best, o);
            int   k2 = __shfl_xor_sync(0xffffffffu, bk, o);
            if (s2 < best || (s2 == best && k2 < bk)) { best = s2; bk = k2; }
        }
        if (lane == 0 && best < 5e8f) {
            float2 dxy = make_float2((float)s_xx[bk], (float)s_yy[bk]);
            int pos = (pi << 16) | pj;
            // bin into every 32x32 output tile whose 52x52 halo contains (pi,pj)
            int tylo = (pi <= 41) ? 0 : ((pi - 41 + 31) >> 5);
            int tyhi = min(TY_N - 1, (pi + 10) >> 5);
            int txlo = (pj <= 41) ? 0 : ((pj - 41 + 31) >> 5);
            int txhi = min(TX_N - 1, (pj + 10) >> 5);
            for (int ty = tylo; ty <= tyhi; ty++)
                for (int tx = txlo; tx <= txhi; tx++) {
                    int tile = (b * TY_N + ty) * TX_N + tx;
                    int idx = atomicAdd(&g_tcnt[tile], 1);
                    if (idx < TCAP) {
                        g_tpos[tile*TCAP + idx] = pos;
                        g_tdxy[tile*TCAP + idx] = dxy;
                    }
                }
        }
    }
}

// ---------------- K2: sparse diffusion; 4 rows per thread, warp-uniform row-band skip ----------------
__global__ void __launch_bounds__(256) k_diffuse(float* __restrict__ out) {
    __shared__ float  s_wk[441];
    __shared__ int    s_pos[TCAP];
    __shared__ float2 s_dxy[TCAP];

    int bb  = blockIdx.z;
    int tid = threadIdx.x;
    int tile = (bb * TY_N + blockIdx.y) * TX_N + blockIdx.x;

    for (int h = tid; h < 441; h += 256) {
        int dy = h / 21 - 10, dx = h % 21 - 10;
        s_wk[h] = expf(-sqrtf((float)(dx*dx + dy*dy)) * 0.2f);
    }
    int m = min(g_tcnt[tile], TCAP);
    for (int h = tid; h < m; h += 256) {
        s_pos[h] = g_tpos[tile*TCAP + h];
        s_dxy[h] = g_tdxy[tile*TCAP + h];
    }
    if (tid == 0) g_tcnt[tile] = 0;   // self-reset: next launch starts from zero, no memset node
    __syncthreads();

    int w = tid >> 5, lane = tid & 31;
    int ox = blockIdx.x * TS + lane;
    int ybase = blockIdx.y * TS + 4*w;   // this thread owns rows ybase..ybase+3, column ox

    float nx0=0.f,ny0=0.f,dn0=0.f, nx1=0.f,ny1=0.f,dn1=0.f;
    float nx2=0.f,ny2=0.f,dn2=0.f, nx3=0.f,ny3=0.f,dn3=0.f;

    for (int pI = 0; pI < m; pI++) {
        int pos = s_pos[pI];
        int dyb = (pos >> 16) - ybase + HALO;      // warp-uniform
        if ((unsigned)dyb > 23u) continue;         // uniform skip of ~55% of entries
        int ddx = (pos & 0xffff) - ox + HALO;
        if ((unsigned)ddx <= 20u) {
            float2 d = s_dxy[pI];
            int base = dyb * 21 + ddx;
            if ((unsigned) dyb      <= 20u) { float wv = s_wk[base];      nx0 += wv*d.x; ny0 += wv*d.y; dn0 += wv; }
            if ((unsigned)(dyb - 1) <= 20u) { float wv = s_wk[base - 21]; nx1 += wv*d.x; ny1 += wv*d.y; dn1 += wv; }
            if ((unsigned)(dyb - 2) <= 20u) { float wv = s_wk[base - 42]; nx2 += wv*d.x; ny2 += wv*d.y; dn2 += wv; }
            if ((unsigned)(dyb - 3) <= 20u) { float wv = s_wk[base - 63]; nx3 += wv*d.x; ny3 += wv*d.y; dn3 += wv; }
        }
    }

    float* outx = out + (bb*2 + 0)*NPIX;
    float* outy = out + (bb*2 + 1)*NPIX;
    int q = ybase * W + ox;
    float fx = (float)ox;
    float i0 = 1.0f/(dn0+1e-6f); outx[q      ] = fx + 0.6f*nx0*i0; outy[q      ] = (float)(ybase  ) + 0.6f*ny0*i0;
    float i1 = 1.0f/(dn1+1e-6f); outx[q +   W] = fx + 0.6f*nx1*i1; outy[q +   W] = (float)(ybase+1) + 0.6f*ny1*i1;
    float i2 = 1.0f/(dn2+1e-6f); outx[q + 2*W] = fx + 0.6f*nx2*i2; outy[q + 2*W] = (float)(ybase+2) + 0.6f*ny2*i2;
    float i3 = 1.0f/(dn3+1e-6f); outx[q + 3*W] = fx + 0.6f*nx3*i3; outy[q + 3*W] = (float)(ybase+3) + 0.6f*ny3*i3;
}

extern "C" void kernel_launch(void* const* d_in, const int* in_sizes, int n_in,
                              void* d_out, int out_size) {
    const float* src = (const float*)d_in[0];
    const float* dst = (const float*)d_in[1];
    const int*   xx  = (const int*)d_in[2];
    const int*   yy  = (const int*)d_in[3];
    int K = in_sizes[2];
    float* out = (float*)d_out;

    dim3 gs(NPIX/1024, BB);
    k_seed<<<gs, 256>>>(src, dst, xx, yy, K);

    dim3 gd(TX_N, TY_N, BB);
    k_diffuse<<<gd, 256>>>(out);
}

// round 6
// speedup vs baseline: 1.2108x; 1.2108x over previous
#include <cuda_runtime.h>
#include <cuda_bf16.h>

#define BB 2
#define H 256
#define W 832
#define NPIX (H*W)

#define TS 32
#define HALO 10
#define TY_N (H/TS)          // 8
#define TX_N (W/TS)          // 26
#define NTILE (TY_N*TX_N)    // 208 per batch
#define TCAP 352             // >= 18*18 = 324 (kept points pairwise Chebyshev >= 3 in 52x52 halo)

// per-tile binned active-point lists (zero-initialized at module load; k_diffuse re-zeroes counts)
__device__ int    g_tcnt[BB*NTILE];
__device__ int    g_tpos[BB*NTILE*TCAP];     // (i<<16)|j
__device__ float2 g_tdxy[BB*NTILE*TCAP];

// on-demand orientation: circular 3x3 box blur + edge-clamped np.gradient -> (cos, sin) of atan2
__device__ __forceinline__ void orient(const float* __restrict__ m, int i, int j,
                                       float& cs, float& ss) {
    float patch[5][5];
#pragma unroll
    for (int r = 0; r < 5; r++) {
        int ii = i + r - 2; ii += (ii < 0) ? H : 0; ii -= (ii >= H) ? H : 0;
#pragma unroll
        for (int c = 0; c < 5; c++) {
            int jj = j + c - 2; jj += (jj < 0) ? W : 0; jj -= (jj >= W) ? W : 0;
            patch[r][c] = m[ii*W + jj];
        }
    }
#define BLUR_AT(di, dj) (patch[1+di][1+dj] + patch[1+di][2+dj] + patch[1+di][3+dj] \
                       + patch[2+di][1+dj] + patch[2+di][2+dj] + patch[2+di][3+dj] \
                       + patch[3+di][1+dj] + patch[3+di][2+dj] + patch[3+di][3+dj])
    float byp = BLUR_AT(1, 0), bym = BLUR_AT(-1, 0), bc = BLUR_AT(0, 0);
    float bxp = BLUR_AT(0, 1), bxm = BLUR_AT(0, -1);
#undef BLUR_AT
    float gyv = (i == 0) ? (byp - bc) : (i == H-1) ? (bc - bym) : 0.5f * (byp - bym);
    float gxv = (j == 0) ? (bxp - bc) : (j == W-1) ? (bc - bxm) : 0.5f * (bxp - bxm);
    float r = sqrtf(gxv*gxv + gyv*gyv);
    if (r > 0.f) { cs = gxv / r; ss = gyv / r; }
    else         { cs = 1.f;     ss = 0.f;     }   // atan2(0,0)=0
}

// ---------------- K1: fused sparsify + correspondence search + tile binning (R4 structure) ----------------
#define STY 8
#define STX 32
__global__ void __launch_bounds__(STY*STX) k_seed(const float* __restrict__ src,
                                                  const float* __restrict__ dst,
                                                  const int* __restrict__ xx,
                                                  const int* __restrict__ yy, int K) {
    __shared__ int s_pos[48];
    __shared__ int s_cnt;

    int b = blockIdx.z;
    int gy0 = blockIdx.y * STY, gx0 = blockIdx.x * STX;
    int tid = threadIdx.y * STX + threadIdx.x;
    const float* S = src + b*NPIX;
    const float* D = dst + b*NPIX;

    if (tid == 0) s_cnt = 0;
    __syncthreads();

    // phase 1: keep-test (min linear index edge in 5x5 window)
    int i = gy0 + threadIdx.y, j = gx0 + threadIdx.x;
    int p = i*W + j;
    if (S[p] > 0.5f) {
        bool kept = true;
#pragma unroll
        for (int a = -2; a <= 2; a++) {
            int ii = i + a;
            if (ii < 0 || ii >= H) continue;
#pragma unroll
            for (int c = -2; c <= 2; c++) {
                int jj = j + c;
                if (jj < 0 || jj >= W) continue;
                int q = ii*W + jj;
                if (q < p && S[q] > 0.5f) kept = false;
            }
        }
        if (kept) { int idx = atomicAdd(&s_cnt, 1); s_pos[idx] = p; }
    }
    __syncthreads();
    int n = s_cnt;

    // phase 2: warp per kept point, K offsets over lanes
    int warp = tid >> 5, lane = tid & 31;
    for (int pt = warp; pt < n; pt += STY*STX/32) {
        int pp = s_pos[pt];
        int pi = pp / W, pj = pp - (pp / W) * W;
        float cs, ssv;
        orient(S, pi, pj, cs, ssv);   // uniform addresses across warp -> broadcast loads
        float best = 1e9f; int bk = 0x7fffffff;
        for (int k = lane; k < K; k += 32) {
            int ox = xx[k], oy = yy[k];
            int ii = pi + oy, jj = pj + ox;
            if (ii >= 0 && ii < H && jj >= 0 && jj < W) {
                int q = ii*W + jj;
                if (D[q] > 0.5f) {
                    float cd, sd;
                    orient(D, ii, jj, cd, sd);   // rare (~2 hits/point)
                    float ang = 1.0f - (cs*cd + ssv*sd);
                    float sc = 20.0f * sqrtf((float)(ox*ox + oy*oy)) + 10.5f * ang;
                    if (sc < best) { best = sc; bk = k; }
                }
            }
        }
        // warp lexicographic (score, k) min -> global first-index-of-min (argmin semantics)
#pragma unroll
        for (int o = 16; o; o >>= 1) {
            float s2 = __shfl_xor_sync(0xffffffffu, best, o);
            int   k2 = __shfl_xor_sync(0xffffffffu, bk, o);
            if (s2 < best || (s2 == best && k2 < bk)) { best = s2; bk = k2; }
        }
        if (lane == 0 && best < 5e8f) {
            float2 dxy = make_float2((float)xx[bk], (float)yy[bk]);
            int pos = (pi << 16) | pj;
            // bin into every 32x32 output tile whose 52x52 halo contains (pi,pj)
            int tylo = (pi <= 41) ? 0 : ((pi - 41 + 31) >> 5);
            int tyhi = min(TY_N - 1, (pi + 10) >> 5);
            int txlo = (pj <= 41) ? 0 : ((pj - 41 + 31) >> 5);
            int txhi = min(TX_N - 1, (pj + 10) >> 5);
            for (int ty = tylo; ty <= tyhi; ty++)
                for (int tx = txlo; tx <= txhi; tx++) {
                    int tile = (b * TY_N + ty) * TX_N + tx;
                    int idx = atomicAdd(&g_tcnt[tile], 1);
                    if (idx < TCAP) {
                        g_tpos[tile*TCAP + idx] = pos;
                        g_tdxy[tile*TCAP + idx] = dxy;
                    }
                }
        }
    }
}

// ---------------- K2: sparse diffusion; 4 rows per thread, warp-uniform row-band skip ----------------
__global__ void __launch_bounds__(256) k_diffuse(float* __restrict__ out) {
    __shared__ float  s_wk[441];
    __shared__ int    s_pos[TCAP];
    __shared__ float2 s_dxy[TCAP];

    int bb  = blockIdx.z;
    int tid = threadIdx.x;
    int tile = (bb * TY_N + blockIdx.y) * TX_N + blockIdx.x;

    for (int h = tid; h < 441; h += 256) {
        int dy = h / 21 - 10, dx = h % 21 - 10;
        s_wk[h] = expf(-sqrtf((float)(dx*dx + dy*dy)) * 0.2f);
    }
    int m = min(g_tcnt[tile], TCAP);
    for (int h = tid; h < m; h += 256) {
        s_pos[h] = g_tpos[tile*TCAP + h];
        s_dxy[h] = g_tdxy[tile*TCAP + h];
    }
    if (tid == 0) g_tcnt[tile] = 0;   // self-reset: next launch starts from zero, no memset node
    __syncthreads();

    int w = tid >> 5, lane = tid & 31;
    int ox = blockIdx.x * TS + lane;
    int ybase = blockIdx.y * TS + 4*w;   // this thread owns rows ybase..ybase+3, column ox

    float nx0=0.f,ny0=0.f,dn0=0.f, nx1=0.f,ny1=0.f,dn1=0.f;
    float nx2=0.f,ny2=0.f,dn2=0.f, nx3=0.f,ny3=0.f,dn3=0.f;

    for (int pI = 0; pI < m; pI++) {
        int pos = s_pos[pI];
        int dyb = (pos >> 16) - ybase + HALO;      // warp-uniform
        if ((unsigned)dyb > 23u) continue;         // uniform skip of ~55% of entries
        int ddx = (pos & 0xffff) - ox + HALO;
        if ((unsigned)ddx <= 20u) {
            float2 d = s_dxy[pI];
            int base = dyb * 21 + ddx;
            if ((unsigned) dyb      <= 20u) { float wv = s_wk[base];      nx0 += wv*d.x; ny0 += wv*d.y; dn0 += wv; }
            if ((unsigned)(dyb - 1) <= 20u) { float wv = s_wk[base - 21]; nx1 += wv*d.x; ny1 += wv*d.y; dn1 += wv; }
            if ((unsigned)(dyb - 2) <= 20u) { float wv = s_wk[base - 42]; nx2 += wv*d.x; ny2 += wv*d.y; dn2 += wv; }
            if ((unsigned)(dyb - 3) <= 20u) { float wv = s_wk[base - 63]; nx3 += wv*d.x; ny3 += wv*d.y; dn3 += wv; }
        }
    }

    float* outx = out + (bb*2 + 0)*NPIX;
    float* outy = out + (bb*2 + 1)*NPIX;
    int q = ybase * W + ox;
    float fx = (float)ox;
    float i0 = 1.0f/(dn0+1e-6f); outx[q      ] = fx + 0.6f*nx0*i0; outy[q      ] = (float)(ybase  ) + 0.6f*ny0*i0;
    float i1 = 1.0f/(dn1+1e-6f); outx[q +   W] = fx + 0.6f*nx1*i1; outy[q +   W] = (float)(ybase+1) + 0.6f*ny1*i1;
    float i2 = 1.0f/(dn2+1e-6f); outx[q + 2*W] = fx + 0.6f*nx2*i2; outy[q + 2*W] = (float)(ybase+2) + 0.6f*ny2*i2;
    float i3 = 1.0f/(dn3+1e-6f); outx[q + 3*W] = fx + 0.6f*nx3*i3; outy[q + 3*W] = (float)(ybase+3) + 0.6f*ny3*i3;
}

extern "C" void kernel_launch(void* const* d_in, const int* in_sizes, int n_in,
                              void* d_out, int out_size) {
    const float* src = (const float*)d_in[0];
    const float* dst = (const float*)d_in[1];
    const int*   xx  = (const int*)d_in[2];
    const int*   yy  = (const int*)d_in[3];
    int K = in_sizes[2];
    float* out = (float*)d_out;

    dim3 gs(W/STX, H/STY, BB), ts(STX, STY);
    k_seed<<<gs, ts>>>(src, dst, xx, yy, K);

    dim3 gd(TX_N, TY_N, BB);
    k_diffuse<<<gd, 256>>>(out);
}